// round 3
// baseline (speedup 1.0000x reference)
#include <cuda_runtime.h>
#include <cstdint>

#define B 8192
#define NNODE 64
#define DOBS 16
#define XROW 18
#define XLEN (B * NNODE * XROW)          // 9437184 floats (x region)
#define EPB 630                          // max edge columns per batch
#define ETOT (B * EPB)                   // 5160960 columns

// Decoupled-lookback status: bits[32:34)=flag (0=invalid,1=aggregate,2=prefix),
// bits[0:32)=value. Single 64-bit word => no ordering fences needed.
__device__ unsigned long long g_status[B];

__global__ void __launch_bounds__(1024) clear_status() {
    int i = blockIdx.x * 1024 + threadIdx.x;
    if (i < B) g_status[i] = 0ULL;
}

__global__ void __launch_bounds__(128) fused_build(const float* __restrict__ obs,
                                                   const float* __restrict__ ego,
                                                   const float* __restrict__ other,
                                                   float* __restrict__ out) {
    int b = blockIdx.x;
    int t = threadIdx.x;              // 0..127
    int lane = t & 31, w = t >> 5;

    __shared__ float st[NNODE * DOBS];     // obs tile, 4KB
    __shared__ int spart[128];
    __shared__ int sord[64];
    __shared__ unsigned sbits[5][2];
    __shared__ unsigned bitmap[128];       // 4096 bits: key = u*64 + v
    __shared__ int warpsum[4];
    __shared__ int sh_off;

    // --- load obs tile (vectorized) + zero bitmap ---
    const float4* src4 = (const float4*)(obs + (size_t)b * NNODE * DOBS);
    float4* st4 = (float4*)st;
#pragma unroll
    for (int i = t; i < NNODE * DOBS / 4; i += 128) st4[i] = src4[i];
    bitmap[t] = 0u;
    __syncthreads();

    // --- write x region: thread t writes 9 contiguous floats at t*9 ---
    {
        int node = t >> 1;
        int d0 = (t & 1) * 9;
        float i0 = (node == 0) ? ego[0] : other[0];
        float i1 = (node == 0) ? ego[1] : other[1];
        float* xout = out + (size_t)b * NNODE * XROW + t * 9;
#pragma unroll
        for (int d = 0; d < 9; d++) {
            int dd = d0 + d;
            float v = (dd < DOBS) ? st[node * DOBS + dd] : (dd == DOBS ? i0 : i1);
            xout[d] = v;
        }
    }

    // --- stable rank by x, split across 128 threads (32 cmp each) ---
    {
        int node = t & 63;
        int jbase = (t >> 6) * 32;
        float xi = st[node * DOBS];
        int r = 0;
#pragma unroll
        for (int jj = 0; jj < 32; jj++) {
            int j = jbase + jj;
            float xj = st[j * DOBS];
            r += (xj < xi) || (xj == xi && j < node);
        }
        spart[t] = r;
    }
    __syncthreads();
    if (t < 64) sord[spart[t] + spart[t + 64]] = t;
    __syncthreads();

    // --- lane masks + chain edges into bitmap ---
    bool mm[5];
    int node = 0;
    if (t < 64) {
        node = sord[t];               // node at sorted position t
        float ys = st[node * DOBS + 1];
        const float T1 = (float)(1.0 / 3.0);
        const float T2 = (float)(2.0 / 3.0);
        bool f0 = (ys <= T1) && (ys > 0.0f);
        bool f1 = (ys > T1) && (ys <= T2);
        bool f2 = (ys >= T2) && (ys < 1.0f);
        mm[0] = f0; mm[1] = f1; mm[2] = f2; mm[3] = f0 || f1; mm[4] = f1 || f2;
#pragma unroll
        for (int m = 0; m < 5; m++) {
            unsigned bal = __ballot_sync(0xffffffffu, mm[m]);
            if (lane == 0) sbits[m][w] = bal;
        }
    }
    __syncthreads();

    if (t < 64) {
#pragma unroll
        for (int m = 0; m < 5; m++) {
            if (mm[m] && t < 63) {
                unsigned long long bits =
                    ((unsigned long long)sbits[m][1] << 32) | (unsigned long long)sbits[m][0];
                unsigned long long rest = bits >> (t + 1);
                if (rest) {
                    int nk = t + 1 + (__ffsll((long long)rest) - 1);
                    int v = sord[nk];
                    int k1 = node * 64 + v;
                    int k2 = v * 64 + node;
                    atomicOr(&bitmap[k1 >> 5], 1u << (k1 & 31));
                    atomicOr(&bitmap[k2 >> 5], 1u << (k2 & 31));
                }
            }
        }
    }
    __syncthreads();

    // --- per-thread popcount + block scan ---
    unsigned wv = bitmap[t];
    int c = __popc(wv);
    int inc = c;
#pragma unroll
    for (int d = 1; d < 32; d <<= 1) {
        int nv = __shfl_up_sync(0xffffffffu, inc, d);
        if (lane >= d) inc += nv;
    }
    if (lane == 31) warpsum[w] = inc;
    __syncthreads();
    int wpre = 0;
#pragma unroll
    for (int j = 0; j < 4; j++) wpre += (j < w) ? warpsum[j] : 0;
    int excl = inc - c + wpre;
    int cnt = warpsum[0] + warpsum[1] + warpsum[2] + warpsum[3];

    // --- publish status + decoupled lookback (warp 0) ---
    if (w == 0) {
        if (b == 0) {
            if (lane == 0) {
                *(volatile unsigned long long*)&g_status[0] =
                    (2ULL << 32) | (unsigned)cnt;
                sh_off = 0;
            }
        } else {
            if (lane == 0)
                *(volatile unsigned long long*)&g_status[b] =
                    (1ULL << 32) | (unsigned)cnt;
            int prefix = 0;
            int idx = b - 1;
            while (true) {
                int j = idx - lane;
                unsigned long long s;
                if (j >= 0) {
                    do {
                        s = *(volatile unsigned long long*)&g_status[j];
                    } while ((unsigned)(s >> 32) == 0u);
                } else {
                    s = (2ULL << 32);    // virtual prefix 0 before array start
                }
                unsigned pm = __ballot_sync(0xffffffffu, (unsigned)(s >> 32) == 2u);
                int val = (int)(unsigned)s;
                if (pm) {
                    int stop = __ffs(pm) - 1;       // closest predecessor w/ prefix
                    int contrib = (lane <= stop) ? val : 0;
#pragma unroll
                    for (int d2 = 16; d2; d2 >>= 1)
                        contrib += __shfl_down_sync(0xffffffffu, contrib, d2);
                    prefix += __shfl_sync(0xffffffffu, contrib, 0);
                    break;
                } else {
                    int contrib = val;
#pragma unroll
                    for (int d2 = 16; d2; d2 >>= 1)
                        contrib += __shfl_down_sync(0xffffffffu, contrib, d2);
                    prefix += __shfl_sync(0xffffffffu, contrib, 0);
                    idx -= 32;
                }
            }
            if (lane == 0) {
                *(volatile unsigned long long*)&g_status[b] =
                    (2ULL << 32) | (unsigned)(prefix + cnt);
                sh_off = prefix;
            }
        }
    }
    __syncthreads();
    int off = sh_off;

    // --- write valid edges directly from bitmap ---
    float* src_out = out + XLEN;
    float* dst_out = out + XLEN + ETOT;
    int nb = b * NNODE;
    {
        int pos = off + excl;
        int kbase = t * 32;
        unsigned bits = wv;
        while (bits) {
            int bit = __ffs(bits) - 1;
            bits &= (bits - 1);
            int k = kbase + bit;
            src_out[pos] = (float)(nb + (k >> 6));
            dst_out[pos] = (float)(nb + (k & 63));
            pos++;
        }
    }

    // --- write this block's exact pad slice: every slot written once ---
    {
        int ps = ETOT - EPB * (b + 1) + off + cnt;
        int pe = ETOT - EPB * b + off;
        for (int i = ps + t; i < pe; i += 128) {
            src_out[i] = -1.0f;
            dst_out[i] = -1.0f;
        }
    }
}

// ---------------------------------------------------------------------------
extern "C" void kernel_launch(void* const* d_in, const int* in_sizes, int n_in,
                              void* d_out, int out_size) {
    const float* obs = (const float*)d_in[0];
    const float* ego = (const float*)d_in[1];
    const float* other = (const float*)d_in[2];
    float* out = (float*)d_out;

    clear_status<<<(B + 1023) / 1024, 1024>>>();
    fused_build<<<B, 128>>>(obs, ego, other, out);
}

// round 5
// speedup vs baseline: 1.4574x; 1.4574x over previous
#include <cuda_runtime.h>
#include <cstdint>

#define B 8192
#define NNODE 64
#define DOBS 16
#define XROW 18
#define XLEN (B * NNODE * XROW)          // 9437184 floats (x region)
#define EPB 630                          // max edge columns per batch
#define ETOT (B * EPB)                   // 5160960 columns
#define KEY_STRIDE 640

__device__ unsigned short g_keys[(size_t)B * KEY_STRIDE];
__device__ int g_cnt[B];
__device__ int g_off[B];
__device__ int g_total;

// ---------------------------------------------------------------------------
// Kernel 1: fused x-write + per-batch edge keys. 128 thr/block.
// ---------------------------------------------------------------------------
__global__ void __launch_bounds__(128) build_edges_x(const float* __restrict__ obs,
                                                     const float* __restrict__ ego,
                                                     const float* __restrict__ other,
                                                     float* __restrict__ out) {
    int b = blockIdx.x;
    int t = threadIdx.x;              // 0..127
    int lane = t & 31, w = t >> 5;

    __shared__ float sx[64], sy[64];
    __shared__ unsigned long long skey[64];
    __shared__ int spart[128];
    __shared__ int sord[64];
    __shared__ unsigned sbits[5][2];
    __shared__ unsigned bitmap[128];       // 4096 bits: key = u*64 + v
    __shared__ int warpsum[4];

    const float4* src4 = (const float4*)(obs + (size_t)b * NNODE * DOBS);
    float* xout = out + (size_t)b * NNODE * XROW;

    float4 fa = src4[t];
    float4 fb = src4[t + 128];
    bitmap[t] = 0u;

    // extract x,y columns (row n starts at float4 index n*4)
    if ((t & 3) == 0) { sx[t >> 2] = fa.x; sy[t >> 2] = fa.y; }
    { int i = t + 128; if ((i & 3) == 0) { sx[i >> 2] = fb.x; sy[i >> 2] = fb.y; } }

    // write obs part of x directly: float4 i -> out row n=i>>2, cols 4(i&3)..+3
    {
        int n = t >> 2, q = t & 3;
        float2* p = (float2*)(xout + n * XROW + q * 4);
        p[0] = make_float2(fa.x, fa.y);
        p[1] = make_float2(fa.z, fa.w);
    }
    {
        int i = t + 128;
        int n = i >> 2, q = i & 3;
        float2* p = (float2*)(xout + n * XROW + q * 4);
        p[0] = make_float2(fb.x, fb.y);
        p[1] = make_float2(fb.z, fb.w);
    }
    // init columns 16,17
    if (t < 64) {
        float2 iv = (t == 0) ? make_float2(ego[0], ego[1])
                             : make_float2(other[0], other[1]);
        *(float2*)(xout + t * XROW + DOBS) = iv;
    }
    __syncthreads();   // sx/sy fully written

    // sortable key: x in [0,1) so float bits preserve order; tie-break by index
    if (t < 64) {
        skey[t] = (((unsigned long long)__float_as_uint(sx[t])) << 6) | (unsigned)t;
    }
    __syncthreads();

    // --- stable rank by x: 128 threads, 32 u64 compares each ---
    {
        int node = t & 63;
        int jbase = (t >> 6) * 32;
        unsigned long long ki = skey[node];
        int r = 0;
#pragma unroll
        for (int jj = 0; jj < 32; jj++) {
            r += (skey[jbase + jj] < ki);
        }
        spart[t] = r;
    }
    __syncthreads();
    if (t < 64) sord[spart[t] + spart[t + 64]] = t;
    __syncthreads();

    // --- lane masks + chain edges into bitmap ---
    bool mm[5];
    int node = 0;
    if (t < 64) {
        node = sord[t];               // node at sorted position t
        float ys = sy[node];
        const float T1 = (float)(1.0 / 3.0);
        const float T2 = (float)(2.0 / 3.0);
        bool f0 = (ys <= T1) && (ys > 0.0f);
        bool f1 = (ys > T1) && (ys <= T2);
        bool f2 = (ys >= T2) && (ys < 1.0f);
        mm[0] = f0; mm[1] = f1; mm[2] = f2; mm[3] = f0 || f1; mm[4] = f1 || f2;
#pragma unroll
        for (int m = 0; m < 5; m++) {
            unsigned bal = __ballot_sync(0xffffffffu, mm[m]);
            if (lane == 0) sbits[m][w] = bal;
        }
    }
    __syncthreads();

    if (t < 64) {
#pragma unroll
        for (int m = 0; m < 5; m++) {
            if (mm[m] && t < 63) {
                unsigned long long bits =
                    ((unsigned long long)sbits[m][1] << 32) | (unsigned long long)sbits[m][0];
                unsigned long long rest = bits >> (t + 1);
                if (rest) {
                    int nk = t + 1 + (__ffsll((long long)rest) - 1);
                    int v = sord[nk];
                    int k1 = node * 64 + v;
                    int k2 = v * 64 + node;
                    atomicOr(&bitmap[k1 >> 5], 1u << (k1 & 31));
                    atomicOr(&bitmap[k2 >> 5], 1u << (k2 & 31));
                }
            }
        }
    }
    __syncthreads();

    // --- compact: each of 128 threads owns one 32-bit bitmap word ---
    unsigned wv = bitmap[t];
    int c = __popc(wv);
    int inc = c;
#pragma unroll
    for (int d = 1; d < 32; d <<= 1) {
        int nv = __shfl_up_sync(0xffffffffu, inc, d);
        if (lane >= d) inc += nv;
    }
    if (lane == 31) warpsum[w] = inc;
    __syncthreads();
    int wpre = 0;
#pragma unroll
    for (int j = 0; j < 4; j++) wpre += (j < w) ? warpsum[j] : 0;
    int excl = inc - c + wpre;
    if (t == 0) g_cnt[b] = warpsum[0] + warpsum[1] + warpsum[2] + warpsum[3];

    unsigned short* kb = g_keys + (size_t)b * KEY_STRIDE;
    int pos = excl;
    int kbase = t * 32;
    while (wv) {
        int bit = __ffs(wv) - 1;
        wv &= (wv - 1);
        kb[pos++] = (unsigned short)(kbase + bit);
    }
}

// ---------------------------------------------------------------------------
// Kernel 2: exclusive scan of g_cnt[8192] -> g_off, + g_total
// ---------------------------------------------------------------------------
__global__ void __launch_bounds__(1024) scan_counts() {
    int t = threadIdx.x;
    int lane = t & 31, wid = t >> 5;
    __shared__ int wsum[32];

    int base = t * 8;
    int v[8];
    int s = 0;
#pragma unroll
    for (int i = 0; i < 8; i++) {
        v[i] = s;
        s += g_cnt[base + i];
    }
    int inc = s;
#pragma unroll
    for (int d = 1; d < 32; d <<= 1) {
        int nv = __shfl_up_sync(0xffffffffu, inc, d);
        if (lane >= d) inc += nv;
    }
    if (lane == 31) wsum[wid] = inc;
    __syncthreads();
    if (wid == 0) {
        int wv = wsum[lane];
        int winc = wv;
#pragma unroll
        for (int d = 1; d < 32; d <<= 1) {
            int nv = __shfl_up_sync(0xffffffffu, winc, d);
            if (lane >= d) winc += nv;
        }
        wsum[lane] = winc - wv;   // exclusive warp offsets
    }
    __syncthreads();
    int excl = inc - s + wsum[wid];
#pragma unroll
    for (int i = 0; i < 8; i++) g_off[base + i] = excl + v[i];
    if (t == 1023) g_total = excl + s;
}

// ---------------------------------------------------------------------------
// Kernel 3: scatter valid edges + this block's share of the -1 pad
// ---------------------------------------------------------------------------
__global__ void __launch_bounds__(256) scatter_pad(float* __restrict__ out) {
    int b = blockIdx.x;
    int t = threadIdx.x;
    int cnt = g_cnt[b];
    int off = g_off[b];
    const unsigned short* kb = g_keys + (size_t)b * KEY_STRIDE;
    float* src_out = out + XLEN;
    float* dst_out = out + XLEN + ETOT;
    int nb = b * NNODE;
    for (int i = t; i < cnt; i += 256) {
        int k = kb[i];
        src_out[off + i] = (float)(nb + (k >> 6));
        dst_out[off + i] = (float)(nb + (k & 63));
    }
    // pad share
    int T = g_total;
    int P = ETOT - T;
    int chunk = (P + B - 1) / B;
    int start = T + b * chunk;
    int end = start + chunk;
    if (end > ETOT) end = ETOT;
    for (int i = start + t; i < end; i += 256) {
        src_out[i] = -1.0f;
        dst_out[i] = -1.0f;
    }
}

// ---------------------------------------------------------------------------
extern "C" void kernel_launch(void* const* d_in, const int* in_sizes, int n_in,
                              void* d_out, int out_size) {
    const float* obs = (const float*)d_in[0];
    const float* ego = (const float*)d_in[1];
    const float* other = (const float*)d_in[2];
    float* out = (float*)d_out;

    build_edges_x<<<B, 128>>>(obs, ego, other, out);
    scan_counts<<<1, 1024>>>();
    scatter_pad<<<B, 256>>>(out);
}